// round 8
// baseline (speedup 1.0000x reference)
#include <cuda_runtime.h>
#include <cuda_bf16.h>

// DifferentiableHMM_Centered — GB300 sm_103a, R8
//
// Math reduction (R1): straight-through gumbel-softmax argmax collapses to
//   norm_copy[s,j] = all_means[argmax_k(log_em_k + gumbel_k)]
//   smooth_loss    = 0.1 * 2 * (#mismatch(state[row],state[col]) over E x Bc) / (E*Bc*3)
//
// R8: phase 1 = R6 exactly (best known; R7 showed it is perturbation-fragile).
// Phase 2 rebuilt: per-warp-per-edge was a pure latency chain (standalone it
// measured ~10us with all pipes <10%). Now SMEM-tiled: each block owns one
// 16B column chunk of the packed state, loads a 2048-row slice (32KB smem),
// and streams its edge subset with 2 x LDS.128 + ~14 ALU per edge. No global
// latency in the inner loop; state re-read is 18 x 1.5MB of L2 (~1-2us).

#define HALF_LOG_2PI 0.9189385332046727f
#define NSM 148
#define BPSM 6
#define NBLOCKS (NSM * BPSM)
#define NT 256
#define MAXROWS 2048

// 2048 rows x 128 u64 capacity (768B used/row). Zero-initialized at module
// load; padding never written -> XOR contributes 0 mismatches.
__device__ unsigned long long g_state[2048 * 128];
__device__ unsigned int g_count;  // mismatch total
__device__ unsigned int g_done;   // finalize ticket
__device__ unsigned int g_bar;    // grid barrier arrival counter

__device__ __forceinline__ void classify(float xv, float g0, float g1, float g2,
                                         float m0, float m2,
                                         float i0, float i1, float i2,
                                         float c0, float c1, float c2,
                                         int& k, float& nv) {
    float z0 = (xv - m0) * i0;
    float z1 = xv * i1;                // middle state mean == 0
    float z2 = (xv - m2) * i2;
    float l0 = fmaf(-0.5f * z0, z0, c0) + g0;
    float l1 = fmaf(-0.5f * z1, z1, c1) + g1;
    float l2 = fmaf(-0.5f * z2, z2, c2) + g2;
    k = 0; float best = l0; nv = m0;
    if (l1 > best) { best = l1; k = 1; nv = 0.0f; }
    if (l2 > best) {            k = 2; nv = m2; }
}

__device__ __forceinline__ unsigned int mismatch16(uint4 a, uint4 b) {
    unsigned long long d0 = ((unsigned long long)(a.y ^ b.y) << 32) | (a.x ^ b.x);
    unsigned long long d1 = ((unsigned long long)(a.w ^ b.w) << 32) | (a.z ^ b.z);
    d0 = (d0 | (d0 >> 1)) & 0x5555555555555555ull;
    d1 = (d1 | (d1 >> 1)) & 0x5555555555555555ull;
    return (unsigned int)(__popcll(d0) + __popcll(d1));
}

__global__ void __launch_bounds__(NT, BPSM)
fused_kernel(const float* __restrict__ x,
             const int*   __restrict__ bin_idx,
             const int*   __restrict__ edge_index,
             const float* __restrict__ gumbel,
             const float* __restrict__ state_means,
             const float* __restrict__ log_stds,
             float*       __restrict__ out,
             float*       __restrict__ loss_out,
             int B, int Bc, int S, int stride_bytes, int stride_u4,
             int E, long long denom) {
    __shared__ float sp[8];
    __shared__ unsigned int sred[NT / 32];
    __shared__ uint4 s_slice[MAXROWS];          // 32 KB column slice

    if (threadIdx.x == 0) {
        float s0 = expf(log_stds[0]) + 1e-6f;
        float s1 = expf(log_stds[1]) + 1e-6f;
        float s2 = expf(log_stds[2]) + 1e-6f;
        sp[0] = state_means[0];
        sp[1] = state_means[1];
        sp[2] = 1.0f / s0;  sp[3] = 1.0f / s1;  sp[4] = 1.0f / s2;
        sp[5] = -logf(s0) - HALF_LOG_2PI;
        sp[6] = -logf(s1) - HALF_LOG_2PI;
        sp[7] = -logf(s2) - HALF_LOG_2PI;
    }
    __syncthreads();

    float m0 = sp[0], m2 = sp[1];
    float i0 = sp[2], i1 = sp[3], i2 = sp[4];
    float c0 = sp[5], c1 = sp[6], c2 = sp[7];

    // -------- Phase 1: state map + norm_copy (identical to R6) --------------
    int groups  = (Bc + 3) >> 2;        // 4 bins -> 1 packed byte
    int items   = S * groups;
    int gstride = gridDim.x * (int)blockDim.x;

    for (int it = blockIdx.x * (int)blockDim.x + threadIdx.x;
         it < items; it += gstride) {
        int s  = it / groups;
        int jt = it - s * groups;
        int j0 = jt << 2;
        size_t rowx = (size_t)s * (size_t)B;
        size_t base = rowx + (size_t)j0;

        bool done = false;
        if ((j0 + 3 < Bc) && ((base & 3) == 0)) {
            // speculative identity-mapped loads, all independent:
            int4   bi = __ldg((const int4*)(bin_idx + j0));
            float4 xv = __ldcs((const float4*)(x + base));
            const float4* gp = (const float4*)(gumbel + base * 3u);
            float4 ga = __ldcs(gp), gb = __ldcs(gp + 1), gc = __ldcs(gp + 2);
            if ((bi.x == j0) & (bi.y == j0 + 1) & (bi.z == j0 + 2) &
                (bi.w == j0 + 3)) {
                int k; unsigned int pack = 0;
                float n0, n1, n2, n3;
                classify(xv.x, ga.x, ga.y, ga.z, m0,m2,i0,i1,i2,c0,c1,c2, k, n0);
                pack  = (unsigned)k;
                classify(xv.y, ga.w, gb.x, gb.y, m0,m2,i0,i1,i2,c0,c1,c2, k, n1);
                pack |= (unsigned)k << 2;
                classify(xv.z, gb.z, gb.w, gc.x, m0,m2,i0,i1,i2,c0,c1,c2, k, n2);
                pack |= (unsigned)k << 4;
                classify(xv.w, gc.y, gc.z, gc.w, m0,m2,i0,i1,i2,c0,c1,c2, k, n3);
                pack |= (unsigned)k << 6;

                size_t oi = (size_t)s * (size_t)Bc + (size_t)j0;
                if ((oi & 3) == 0) {
                    __stcs((float4*)(out + oi), make_float4(n0, n1, n2, n3));
                } else {
                    out[oi+0]=n0; out[oi+1]=n1; out[oi+2]=n2; out[oi+3]=n3;
                }
                ((unsigned char*)g_state)[(size_t)s * (size_t)stride_bytes +
                                          (size_t)jt] = (unsigned char)pack;
                done = true;
            }
        }
        if (!done) {
            // generic scalar fallback
            unsigned int pack = 0;
            float nv[4] = {0.f, 0.f, 0.f, 0.f};
            for (int u = 0; u < 4; ++u) {
                int j = j0 + u;
                if (j >= Bc) break;
                int src = __ldg(bin_idx + j);
                size_t xi = rowx + (size_t)src;
                float xvs = __ldg(x + xi);
                const float* g = gumbel + xi * 3u;
                int k;
                classify(xvs, __ldg(g), __ldg(g+1), __ldg(g+2),
                         m0,m2,i0,i1,i2,c0,c1,c2, k, nv[u]);
                pack |= (unsigned)k << (2 * u);
            }
            size_t oi = (size_t)s * (size_t)Bc + (size_t)j0;
            for (int u = 0; u < 4; ++u)
                if (j0 + u < Bc) out[oi + u] = nv[u];
            ((unsigned char*)g_state)[(size_t)s * (size_t)stride_bytes +
                                      (size_t)jt] = (unsigned char)pack;
        }
    }

    // -------- Grid barrier (all blocks resident by construction) ------------
    __syncthreads();
    if (threadIdx.x == 0) {
        __threadfence();                         // release state writes
        unsigned int a = atomicAdd(&g_bar, 1u) + 1u;
        if (a < gridDim.x) {
            volatile unsigned int* vb = &g_bar;
            while (*vb < gridDim.x) { }
        }
        __threadfence();                         // acquire before state reads
    }
    __syncthreads();

    // -------- Phase 2: SMEM-tiled edge mismatch count -----------------------
    int warp = threadIdx.x >> 5;
    int lane = threadIdx.x & 31;
    int wpb  = (int)blockDim.x >> 5;
    unsigned int cnt = 0;

    if (stride_u4 <= 48 && S <= MAXROWS) {
        int nchunk   = stride_u4;                     // 16B chunks per row
        int negroups = gridDim.x / nchunk;            // edge groups
        int active   = nchunk * negroups;
        if ((int)blockIdx.x < active) {
            int chunk = (int)blockIdx.x % nchunk;
            int eg    = (int)blockIdx.x / nchunk;
            int ep    = (E + negroups - 1) / negroups;
            int es    = eg * ep;
            int ee    = min(es + ep, E);

            // load this chunk's column slice: S rows x 16B -> smem
            const uint4* gsc = (const uint4*)g_state + chunk;
            for (int r = threadIdx.x; r < S; r += (int)blockDim.x)
                s_slice[r] = __ldg(gsc + (size_t)r * (size_t)stride_u4);
            __syncthreads();

            for (int e = es + (int)threadIdx.x; e < ee; e += (int)blockDim.x) {
                int r = __ldg(edge_index + e);
                int c = __ldg(edge_index + E + e);
                cnt += mismatch16(s_slice[r], s_slice[c]);  // r==c -> 0
            }
        }
    } else {
        // fallback: warp per edge over global state
        int gwarp  = (int)blockIdx.x * wpb + warp;
        int nwarps = (int)gridDim.x * wpb;
        for (int e = gwarp; e < E; e += nwarps) {
            int r = __ldg(edge_index + e);
            int c = __ldg(edge_index + E + e);
            if (r == c) continue;
            const uint4* a = (const uint4*)g_state + (size_t)r * (size_t)stride_u4;
            const uint4* b = (const uint4*)g_state + (size_t)c * (size_t)stride_u4;
            for (int w = lane; w < stride_u4; w += 32)
                cnt += mismatch16(__ldg(a + w), __ldg(b + w));
        }
    }

    cnt = __reduce_add_sync(0xffffffffu, cnt);
    if (lane == 0) sred[warp] = cnt;
    __syncthreads();

    // -------- Finalize (ticketed; winner writes loss + resets counters) -----
    if (threadIdx.x == 0) {
        unsigned int tot = 0;
        for (int i = 0; i < wpb; ++i) tot += sred[i];
        if (tot) atomicAdd(&g_count, tot);
        __threadfence();
        unsigned int ticket = atomicAdd(&g_done, 1u);
        if (ticket == gridDim.x - 1u) {
            unsigned int totalc = atomicAdd(&g_count, 0u);   // ordered read
            loss_out[0] = (float)(0.2 * (double)totalc / (double)denom);
            g_count = 0u;            // reset for next graph replay
            g_done  = 0u;
            g_bar   = 0u;
        }
    }
}

extern "C" void kernel_launch(void* const* d_in, const int* in_sizes, int n_in,
                              void* d_out, int out_size) {
    const float* x           = (const float*)d_in[0];
    const int*   bin_idx     = (const int*)  d_in[1];
    const int*   edge_index  = (const int*)  d_in[2];
    const float* gumbel      = (const float*)d_in[3];
    const float* state_means = (const float*)d_in[4];
    const float* log_stds    = (const float*)d_in[5];
    float* out = (float*)d_out;

    int Bc = in_sizes[1];          // covered bins (output columns)
    int E  = in_sizes[2] / 2;      // edges
    int B  = Bc;                   // ranges cover all bins => B == Bc
    int S  = in_sizes[0] / B;      // spots

    int groups       = (Bc + 3) / 4;              // packed bytes per row
    int words        = (groups + 7) / 8;          // u64 words used
    int stride_words = (words + 15) & ~15;        // pad to 128B
    if (stride_words > 128) stride_words = 128;   // capacity guard
    int stride_bytes = stride_words * 8;
    int stride_u4    = stride_words / 2;

    long long denom = (long long)E * (long long)Bc * 3ll;

    fused_kernel<<<NBLOCKS, NT>>>(
        x, bin_idx, edge_index, gumbel, state_means, log_stds,
        out, out + ((size_t)out_size - 1),
        B, Bc, S, stride_bytes, stride_u4, E, denom);
}

// round 9
// speedup vs baseline: 1.8441x; 1.8441x over previous
#include <cuda_runtime.h>
#include <cuda_bf16.h>

// DifferentiableHMM_Centered — GB300 sm_103a, R9
//
// Math reduction (R1): straight-through gumbel-softmax argmax collapses to
//   norm_copy[s,j] = all_means[argmax_k(log_em_k + gumbel_k)]
//   smooth_loss    = 0.1 * 2 * (#mismatch(state[row],state[col]) over E x Bc) / (E*Bc*3)
//
// R9 = R6 (best: 29.2us) + division-free phase-1 index stepping.
// R6 ncu showed alu pipe at 20%: the per-iteration `it / groups` (runtime
// divisor -> ~20 IMAD ops) sits on the address-generation critical path.
// Host precomputes q = gstride/groups, rm = gstride%groups; the loop carries
// (s, jt) with an add + conditional correction instead.
// R8 lesson: no big static smem (L1 carveout destroyed phase-1 BW).

#define HALF_LOG_2PI 0.9189385332046727f
#define NSM 148
#define BPSM 6
#define NBLOCKS (NSM * BPSM)
#define NT 256

// 2048 rows x 128 u64 capacity (768B used/row). Zero-initialized at module
// load; padding never written -> XOR contributes 0 mismatches.
__device__ unsigned long long g_state[2048 * 128];
__device__ unsigned int g_count;  // mismatch total
__device__ unsigned int g_done;   // finalize ticket
__device__ unsigned int g_bar;    // grid barrier arrival counter

__device__ __forceinline__ void classify(float xv, float g0, float g1, float g2,
                                         float m0, float m2,
                                         float i0, float i1, float i2,
                                         float c0, float c1, float c2,
                                         int& k, float& nv) {
    float z0 = (xv - m0) * i0;
    float z1 = xv * i1;                // middle state mean == 0
    float z2 = (xv - m2) * i2;
    float l0 = fmaf(-0.5f * z0, z0, c0) + g0;
    float l1 = fmaf(-0.5f * z1, z1, c1) + g1;
    float l2 = fmaf(-0.5f * z2, z2, c2) + g2;
    k = 0; float best = l0; nv = m0;
    if (l1 > best) { best = l1; k = 1; nv = 0.0f; }
    if (l2 > best) {            k = 2; nv = m2; }
}

__device__ __forceinline__ unsigned int mismatch16(uint4 a, uint4 b) {
    unsigned long long d0 = ((unsigned long long)(a.y ^ b.y) << 32) | (a.x ^ b.x);
    unsigned long long d1 = ((unsigned long long)(a.w ^ b.w) << 32) | (a.z ^ b.z);
    d0 = (d0 | (d0 >> 1)) & 0x5555555555555555ull;
    d1 = (d1 | (d1 >> 1)) & 0x5555555555555555ull;
    return (unsigned int)(__popcll(d0) + __popcll(d1));
}

__global__ void __launch_bounds__(NT, BPSM)
fused_kernel(const float* __restrict__ x,
             const int*   __restrict__ bin_idx,
             const int*   __restrict__ edge_index,
             const float* __restrict__ gumbel,
             const float* __restrict__ state_means,
             const float* __restrict__ log_stds,
             float*       __restrict__ out,
             float*       __restrict__ loss_out,
             int B, int Bc, int S, int stride_bytes, int stride_u4,
             int E, long long denom, int q_step, int r_step) {
    __shared__ float sp[8];
    __shared__ unsigned int sred[NT / 32];

    if (threadIdx.x == 0) {
        float s0 = expf(log_stds[0]) + 1e-6f;
        float s1 = expf(log_stds[1]) + 1e-6f;
        float s2 = expf(log_stds[2]) + 1e-6f;
        sp[0] = state_means[0];
        sp[1] = state_means[1];
        sp[2] = 1.0f / s0;  sp[3] = 1.0f / s1;  sp[4] = 1.0f / s2;
        sp[5] = -logf(s0) - HALF_LOG_2PI;
        sp[6] = -logf(s1) - HALF_LOG_2PI;
        sp[7] = -logf(s2) - HALF_LOG_2PI;
    }
    __syncthreads();

    float m0 = sp[0], m2 = sp[1];
    float i0 = sp[2], i1 = sp[3], i2 = sp[4];
    float c0 = sp[5], c1 = sp[6], c2 = sp[7];

    // -------- Phase 1: state map + norm_copy, division-free stepping --------
    int groups  = (Bc + 3) >> 2;        // 4 bins -> 1 packed byte
    int items   = S * groups;
    int gstride = gridDim.x * (int)blockDim.x;

    int it0 = blockIdx.x * (int)blockDim.x + threadIdx.x;
    int s   = it0 / groups;             // one division at entry only
    int jt  = it0 - s * groups;

    for (int it = it0; it < items; it += gstride) {
        int j0 = jt << 2;
        size_t rowx = (size_t)s * (size_t)B;
        size_t base = rowx + (size_t)j0;

        bool done = false;
        if ((j0 + 3 < Bc) && ((base & 3) == 0)) {
            // speculative identity-mapped loads, all independent:
            int4   bi = __ldg((const int4*)(bin_idx + j0));
            float4 xv = __ldcs((const float4*)(x + base));
            const float4* gp = (const float4*)(gumbel + base * 3u);
            float4 ga = __ldcs(gp), gb = __ldcs(gp + 1), gc = __ldcs(gp + 2);
            if ((bi.x == j0) & (bi.y == j0 + 1) & (bi.z == j0 + 2) &
                (bi.w == j0 + 3)) {
                int k; unsigned int pack = 0;
                float n0, n1, n2, n3;
                classify(xv.x, ga.x, ga.y, ga.z, m0,m2,i0,i1,i2,c0,c1,c2, k, n0);
                pack  = (unsigned)k;
                classify(xv.y, ga.w, gb.x, gb.y, m0,m2,i0,i1,i2,c0,c1,c2, k, n1);
                pack |= (unsigned)k << 2;
                classify(xv.z, gb.z, gb.w, gc.x, m0,m2,i0,i1,i2,c0,c1,c2, k, n2);
                pack |= (unsigned)k << 4;
                classify(xv.w, gc.y, gc.z, gc.w, m0,m2,i0,i1,i2,c0,c1,c2, k, n3);
                pack |= (unsigned)k << 6;

                size_t oi = (size_t)s * (size_t)Bc + (size_t)j0;
                if ((oi & 3) == 0) {
                    __stcs((float4*)(out + oi), make_float4(n0, n1, n2, n3));
                } else {
                    out[oi+0]=n0; out[oi+1]=n1; out[oi+2]=n2; out[oi+3]=n3;
                }
                ((unsigned char*)g_state)[(size_t)s * (size_t)stride_bytes +
                                          (size_t)jt] = (unsigned char)pack;
                done = true;
            }
        }
        if (!done) {
            // generic scalar fallback
            unsigned int pack = 0;
            float nv[4] = {0.f, 0.f, 0.f, 0.f};
            for (int u = 0; u < 4; ++u) {
                int j = j0 + u;
                if (j >= Bc) break;
                int src = __ldg(bin_idx + j);
                size_t xi = rowx + (size_t)src;
                float xvs = __ldg(x + xi);
                const float* g = gumbel + xi * 3u;
                int k;
                classify(xvs, __ldg(g), __ldg(g+1), __ldg(g+2),
                         m0,m2,i0,i1,i2,c0,c1,c2, k, nv[u]);
                pack |= (unsigned)k << (2 * u);
            }
            size_t oi = (size_t)s * (size_t)Bc + (size_t)j0;
            for (int u = 0; u < 4; ++u)
                if (j0 + u < Bc) out[oi + u] = nv[u];
            ((unsigned char*)g_state)[(size_t)s * (size_t)stride_bytes +
                                      (size_t)jt] = (unsigned char)pack;
        }

        // division-free step: it += gstride  <=>  s += q_step, jt += r_step
        s  += q_step;
        jt += r_step;
        if (jt >= groups) { jt -= groups; ++s; }
    }

    // -------- Grid barrier (all blocks resident by construction) ------------
    __syncthreads();
    if (threadIdx.x == 0) {
        __threadfence();                         // release state writes
        unsigned int a = atomicAdd(&g_bar, 1u) + 1u;
        if (a < gridDim.x) {
            volatile unsigned int* vb = &g_bar;
            while (*vb < gridDim.x) { }
        }
        __threadfence();                         // acquire before state reads
    }
    __syncthreads();

    // -------- Phase 2: edge mismatch count (warp per edge, grid-stride) -----
    int warp = threadIdx.x >> 5;
    int lane = threadIdx.x & 31;
    int wpb  = (int)blockDim.x >> 5;
    int gwarp  = blockIdx.x * wpb + warp;
    int nwarps = gridDim.x * wpb;

    unsigned int cnt = 0;
    for (int e = gwarp; e < E; e += nwarps) {
        int r = __ldg(edge_index + e);
        int c = __ldg(edge_index + E + e);
        if (r == c) continue;
        const uint4* a = (const uint4*)g_state + (size_t)r * (size_t)stride_u4;
        const uint4* b = (const uint4*)g_state + (size_t)c * (size_t)stride_u4;
        if (stride_u4 <= 64) {
            bool p1 = lane + 32 < stride_u4;     // lane < stride_u4 (>=32) always
            uint4 va0 = __ldg(a + lane), vb0 = __ldg(b + lane);
            uint4 va1 = make_uint4(0,0,0,0), vb1 = va1;
            if (p1) { va1 = __ldg(a + lane + 32); vb1 = __ldg(b + lane + 32); }
            cnt += mismatch16(va0, vb0);
            if (p1) cnt += mismatch16(va1, vb1);
        } else {
            for (int w = lane; w < stride_u4; w += 32)
                cnt += mismatch16(__ldg(a + w), __ldg(b + w));
        }
    }
    cnt = __reduce_add_sync(0xffffffffu, cnt);
    if (lane == 0) sred[warp] = cnt;
    __syncthreads();

    // -------- Finalize (ticketed; winner writes loss + resets counters) -----
    if (threadIdx.x == 0) {
        unsigned int tot = 0;
        for (int i = 0; i < wpb; ++i) tot += sred[i];
        if (tot) atomicAdd(&g_count, tot);
        __threadfence();
        unsigned int ticket = atomicAdd(&g_done, 1u);
        if (ticket == gridDim.x - 1u) {
            unsigned int totalc = atomicAdd(&g_count, 0u);   // ordered read
            loss_out[0] = (float)(0.2 * (double)totalc / (double)denom);
            g_count = 0u;            // reset for next graph replay
            g_done  = 0u;
            g_bar   = 0u;
        }
    }
}

extern "C" void kernel_launch(void* const* d_in, const int* in_sizes, int n_in,
                              void* d_out, int out_size) {
    const float* x           = (const float*)d_in[0];
    const int*   bin_idx     = (const int*)  d_in[1];
    const int*   edge_index  = (const int*)  d_in[2];
    const float* gumbel      = (const float*)d_in[3];
    const float* state_means = (const float*)d_in[4];
    const float* log_stds    = (const float*)d_in[5];
    float* out = (float*)d_out;

    int Bc = in_sizes[1];          // covered bins (output columns)
    int E  = in_sizes[2] / 2;      // edges
    int B  = Bc;                   // ranges cover all bins => B == Bc
    int S  = in_sizes[0] / B;      // spots

    int groups       = (Bc + 3) / 4;              // packed bytes per row
    int words        = (groups + 7) / 8;          // u64 words used
    int stride_words = (words + 15) & ~15;        // pad to 128B
    if (stride_words > 128) stride_words = 128;   // capacity guard
    int stride_bytes = stride_words * 8;
    int stride_u4    = stride_words / 2;

    long long denom = (long long)E * (long long)Bc * 3ll;

    int gstride = NBLOCKS * NT;
    int q_step  = gstride / groups;
    int r_step  = gstride - q_step * groups;

    fused_kernel<<<NBLOCKS, NT>>>(
        x, bin_idx, edge_index, gumbel, state_means, log_stds,
        out, out + ((size_t)out_size - 1),
        B, Bc, S, stride_bytes, stride_u4, E, denom, q_step, r_step);
}